// round 9
// baseline (speedup 1.0000x reference)
#include <cuda_runtime.h>
#include <math.h>

#define N_NODES 25000
#define N_EDGES 400000
#define HIDDEN  128
#define NUM_RBF 50
#define CUTOFF_R 10.0f

// Output layout (floats): h_updated, v_updated, f_updated, angular_info, dihedral_info, direction_units
#define O_H   0
#define O_V   3200000
#define O_F   12800000
#define O_ANG 64000000
#define O_DIH 67200000
#define O_DU  118400000

// ---------------- scratch ----------------
__device__ float4 g_u4[N_EDGES];         // (ux, uy, uz, cutoff_w)
__device__ float g_hAV[N_NODES * 256];   // h @ (W_msgA @ W_vec)  (gathered at col)
__device__ float g_hBV[N_NODES * 256];   // h @ (W_msgB @ W_vec)  (gathered at row)
__device__ float g_WAV[128 * 256];
__device__ float g_WBV[128 * 256];
__device__ float g_WRV[NUM_RBF * 256];
__device__ float g_bV[256];              // b_msg @ W_vec + b_vec
__device__ float g_csA[HIDDEN];
__device__ float g_csD[HIDDEN];

typedef unsigned long long u64;

__device__ __forceinline__ u64 pack2s(float x) {   // (x, x)
    u64 r; unsigned int xi = __float_as_uint(x);
    asm("mov.b64 %0, {%1, %1};" : "=l"(r) : "r"(xi)); return r;
}
__device__ __forceinline__ u64 fma2(u64 a, u64 b, u64 c) {
    u64 d; asm("fma.rn.f32x2 %0, %1, %2, %3;" : "=l"(d) : "l"(a), "l"(b), "l"(c)); return d;
}
__device__ __forceinline__ float2 unpack2(u64 a) {
    unsigned int l, h;
    asm("mov.b64 {%0, %1}, %2;" : "=r"(l), "=r"(h) : "l"(a));
    return make_float2(__uint_as_float(l), __uint_as_float(h));
}
__device__ __forceinline__ float sigmoidf_(float x) { return 1.0f / (1.0f + expf(-x)); }

// ---------------- K1: combined prep — du zero, W products, colsums, fused bias ----------------
// grid = 307 blocks x 128 threads.
// all blocks: grid-stride zero of direction_units region.
// blocks 0..305: row r of W_msg(306x128) @ W_vec(128x256).
// block 306:     colsums of W_ang/W_dih + (b_msg @ W_vec + b_vec).
__global__ void k_prepAll(const float* __restrict__ W_msg, const float* __restrict__ W_vec,
                          const float* __restrict__ W_ang, const float* __restrict__ W_dih,
                          const float* __restrict__ b_msg, const float* __restrict__ b_vec,
                          float* __restrict__ du) {
    int r = blockIdx.x;
    int k = threadIdx.x;
    for (int t = r * 128 + k; t < N_NODES * 3; t += 307 * 128) du[t] = 0.0f;

    if (r < 306) {
        __shared__ float wr[HIDDEN];
        wr[k] = W_msg[r * HIDDEN + k];
        __syncthreads();
        float a = 0.f, b = 0.f;
        #pragma unroll 4
        for (int t = 0; t < HIDDEN; t++) {
            float w = wr[t];
            a += w * W_vec[t * 256 + k];
            b += w * W_vec[t * 256 + 128 + k];
        }
        float* dst = (r < 128) ? &g_WAV[r * 256]
                   : (r < 256) ? &g_WBV[(r - 128) * 256]
                               : &g_WRV[(r - 256) * 256];
        dst[k] = a; dst[128 + k] = b;
    } else {
        float a = 0.f, d = 0.f, b1 = 0.f, b2 = 0.f;
        #pragma unroll 4
        for (int j = 0; j < HIDDEN; j++) {
            a += W_ang[j * HIDDEN + k];
            d += W_dih[j * HIDDEN + k];
            float bm = b_msg[j];
            b1 += bm * W_vec[j * 256 + k];
            b2 += bm * W_vec[j * 256 + 128 + k];
        }
        g_csA[k] = a; g_csD[k] = d;
        g_bV[k]       = b1 + b_vec[k];
        g_bV[128 + k] = b2 + b_vec[128 + k];
    }
}

// ---------------- K2: edge geometry + direction_units scatter ----------------
__global__ void k_geom(const float* __restrict__ pos, const int* __restrict__ ei,
                       float* __restrict__ du) {
    int e = blockIdx.x * blockDim.x + threadIdx.x;
    if (e >= N_EDGES) return;
    int r = ei[e];
    int c = ei[N_EDGES + e];
    float dx = pos[c * 3 + 0] - pos[r * 3 + 0];
    float dy = pos[c * 3 + 1] - pos[r * 3 + 1];
    float dz = pos[c * 3 + 2] - pos[r * 3 + 2];
    float dist = sqrtf(dx * dx + dy * dy + dz * dz) + 1e-8f;
    float inv = 1.0f / dist;
    float ux = dx * inv, uy = dy * inv, uz = dz * inv;
    float cw = (dist < CUTOFF_R)
             ? 0.5f * (cosf(3.14159265358979323846f * dist / CUTOFF_R) + 1.0f)
             : 0.0f;
    g_u4[e] = make_float4(ux, uy, uz, cw);
    atomicAdd(&du[r * 3 + 0],  ux);
    atomicAdd(&du[r * 3 + 1],  uy);
    atomicAdd(&du[r * 3 + 2],  uz);
    atomicAdd(&du[c * 3 + 0], -ux);
    atomicAdd(&du[c * 3 + 1], -uy);
    atomicAdd(&du[c * 3 + 2], -uz);
}

// ---------------- K3: per-node — hAV, hBV, h_updated, angular_info ----------------
// 8 nodes per block, 128 threads. Activations j-major; packed f32x2 over node pairs.
__global__ void __launch_bounds__(128) k_node(
        const float* __restrict__ h,
        const float* __restrict__ W_scalar,
        const float* __restrict__ b_scalar,
        const float* __restrict__ b_ang,
        const float* __restrict__ du,
        float* __restrict__ out) {
    int n0 = blockIdx.x * 8;           // N_NODES % 8 == 0
    int k = threadIdx.x;
    __shared__ __align__(16) float hs[HIDDEN][8];   // [j][node]
    __shared__ float angs[8];
    #pragma unroll
    for (int i = 0; i < 8; i++) hs[k][i] = h[(size_t)(n0 + i) * HIDDEN + k];
    if (k < 8) {
        int n = n0 + k;
        float x = du[n * 3 + 0], y = du[n * 3 + 1], z = du[n * 3 + 2];
        angs[k] = x * x + y * y + z * z;
    }
    __syncthreads();

    u64 aA1[4], aA2[4], aB1[4], aB2[4], aS[4];
    #pragma unroll
    for (int p = 0; p < 4; p++) { aA1[p]=0; aA2[p]=0; aB1[p]=0; aB2[p]=0; aS[p]=0; }

    #pragma unroll 2
    for (int j = 0; j < HIDDEN; j++) {
        u64 wA1 = pack2s(g_WAV[j * 256 + k]);
        u64 wA2 = pack2s(g_WAV[j * 256 + 128 + k]);
        u64 wB1 = pack2s(g_WBV[j * 256 + k]);
        u64 wB2 = pack2s(g_WBV[j * 256 + 128 + k]);
        u64 wS  = pack2s(W_scalar[j * HIDDEN + k]);
        ulonglong2 sa = *reinterpret_cast<const ulonglong2*>(&hs[j][0]);
        ulonglong2 sb = *reinterpret_cast<const ulonglong2*>(&hs[j][4]);
        u64 s[4] = {sa.x, sa.y, sb.x, sb.y};
        #pragma unroll
        for (int p = 0; p < 4; p++) {
            aA1[p] = fma2(s[p], wA1, aA1[p]);
            aA2[p] = fma2(s[p], wA2, aA2[p]);
            aB1[p] = fma2(s[p], wB1, aB1[p]);
            aB2[p] = fma2(s[p], wB2, aB2[p]);
            aS[p]  = fma2(s[p], wS,  aS[p]);
        }
    }

    float csA = g_csA[k], ba = b_ang[k], bs = b_scalar[k];
    #pragma unroll
    for (int p = 0; p < 4; p++) {
        float2 vA1 = unpack2(aA1[p]), vA2 = unpack2(aA2[p]);
        float2 vB1 = unpack2(aB1[p]), vB2 = unpack2(aB2[p]);
        float2 vS  = unpack2(aS[p]);
        float A1[2] = {vA1.x, vA1.y}, A2[2] = {vA2.x, vA2.y};
        float B1[2] = {vB1.x, vB1.y}, B2[2] = {vB2.x, vB2.y};
        float S [2] = {vS.x,  vS.y};
        #pragma unroll
        for (int l = 0; l < 2; l++) {
            int i = 2 * p + l;
            int n = n0 + i;
            g_hAV[(size_t)n * 256 + k]       = A1[l];
            g_hAV[(size_t)n * 256 + 128 + k] = A2[l];
            g_hBV[(size_t)n * 256 + k]       = B1[l];
            g_hBV[(size_t)n * 256 + 128 + k] = B2[l];
            float ang  = angs[i];
            float gate = sigmoidf_(ang * csA + ba);
            out[O_H   + (size_t)n * HIDDEN + k] = hs[k][i] + (S[l] + bs) * gate;
            out[O_ANG + (size_t)n * HIDDEN + k] = ang;
        }
    }
}

// ---------------- K4: fused vec path — rbf mini-GEMM + gathers + vec_msg scatter ----------------
// 32 edges per block, 128 threads; message tile double-buffered in halves of 16.
__global__ void __launch_bounds__(128) k_edge(
        const float* __restrict__ v, const int* __restrict__ ei,
        const float* __restrict__ rbf, float* __restrict__ out_v) {
    const int EB = 32;
    int e0 = blockIdx.x * EB;          // N_EDGES % 32 == 0
    int k = threadIdx.x;
    __shared__ __align__(16) float rs[NUM_RBF][EB];     // [rbf][edge]
    __shared__ __align__(16) float m[16][3 * HIDDEN];   // messages (half tile)
    __shared__ float4 s_u4[EB];
    __shared__ int s_row[EB], s_col[EB];

    for (int t = k; t < EB * NUM_RBF; t += 128) {
        int i = t / NUM_RBF, r = t - i * NUM_RBF;
        rs[r][i] = rbf[(size_t)(e0 + i) * NUM_RBF + r];
    }
    if (k < EB) {
        int e = e0 + k;
        s_row[k] = ei[e]; s_col[k] = ei[N_EDGES + e];
        s_u4[k] = g_u4[e];
    }
    __syncthreads();

    u64 a1[16], a2[16];
    #pragma unroll
    for (int p = 0; p < 16; p++) { a1[p] = 0; a2[p] = 0; }

    #pragma unroll 2
    for (int r = 0; r < NUM_RBF; r++) {
        u64 w1 = pack2s(g_WRV[r * 256 + k]);
        u64 w2 = pack2s(g_WRV[r * 256 + 128 + k]);
        #pragma unroll
        for (int q = 0; q < 8; q++) {
            ulonglong2 s2 = *reinterpret_cast<const ulonglong2*>(&rs[r][4 * q]);
            a1[2 * q]     = fma2(s2.x, w1, a1[2 * q]);
            a2[2 * q]     = fma2(s2.x, w2, a2[2 * q]);
            a1[2 * q + 1] = fma2(s2.y, w1, a1[2 * q + 1]);
            a2[2 * q + 1] = fma2(s2.y, w2, a2[2 * q + 1]);
        }
    }

    float bV1 = g_bV[k], bV2 = g_bV[128 + k];

    #pragma unroll
    for (int half = 0; half < 2; half++) {
        #pragma unroll 4
        for (int idx = 0; idx < 16; idx++) {
            int e = half * 16 + idx;       // edge index within block
            int p = e >> 1, lane = e & 1;
            float2 f1 = unpack2(a1[p]), f2 = unpack2(a2[p]);
            float r1 = lane ? f1.y : f1.x;
            float r2 = lane ? f2.y : f2.x;
            int r_ = s_row[e], c_ = s_col[e];
            float4 u = s_u4[e];
            float w1 = (r1 + g_hAV[(size_t)c_ * 256 + k]
                           + g_hBV[(size_t)r_ * 256 + k] + bV1) * u.w;
            float w2 = (r2 + g_hAV[(size_t)c_ * 256 + 128 + k]
                           + g_hBV[(size_t)r_ * 256 + 128 + k] + bV2) * u.w;
            const float* vr = v + (size_t)r_ * 3 * HIDDEN;
            m[idx][k]              = w1 * u.x + w2 * vr[k];
            m[idx][HIDDEN + k]     = w1 * u.y + w2 * vr[HIDDEN + k];
            m[idx][2 * HIDDEN + k] = w1 * u.z + w2 * vr[2 * HIDDEN + k];
        }
        __syncthreads();
        for (int t = k; t < 16 * 96; t += 128) {
            int i = t / 96, q = t - i * 96;
            float4 val = *reinterpret_cast<float4*>(&m[i][q * 4]);
            int c_ = s_col[half * 16 + i];
            atomicAdd(reinterpret_cast<float4*>(out_v + (size_t)c_ * 3 * HIDDEN + q * 4), val);
        }
        __syncthreads();
    }
}

// ---------------- K5: dihedral + f gating — 64 edges/block, packed f32x2 ----------------
__global__ void __launch_bounds__(128) k_fgate(
        const float* __restrict__ f, const int* __restrict__ ei,
        const float* __restrict__ W_edge, const float* __restrict__ b_edge,
        const float* __restrict__ b_dih, const float* __restrict__ du,
        float* __restrict__ out) {
    const int EB = 64;
    int e0 = blockIdx.x * EB;          // N_EDGES % 64 == 0
    int k = threadIdx.x;
    __shared__ __align__(16) float fs[HIDDEN][EB];   // [j][edge]  32KB
    __shared__ float dihs[EB];
    #pragma unroll
    for (int i = 0; i < EB; i++) fs[k][i] = f[(size_t)(e0 + i) * HIDDEN + k];
    if (k < EB) {
        int e = e0 + k;
        int r = ei[e], c = ei[N_EDGES + e];
        float4 u = g_u4[e];
        float vix = du[r * 3 + 0], viy = du[r * 3 + 1], viz = du[r * 3 + 2];
        float vjx = du[c * 3 + 0], vjy = du[c * 3 + 1], vjz = du[c * 3 + 2];
        float di = vix * u.x + viy * u.y + viz * u.z;
        float dj = vjx * u.x + vjy * u.y + vjz * u.z;
        float ax = vix - di * u.x, ay = viy - di * u.y, az = viz - di * u.z;
        float bx = vjx - dj * u.x, by = vjy - dj * u.y, bz = vjz - dj * u.z;
        dihs[k] = ax * bx + ay * by + az * bz;
    }
    __syncthreads();

    u64 acc[32];
    #pragma unroll
    for (int p = 0; p < 32; p++) acc[p] = 0;

    for (int j = 0; j < HIDDEN; j++) {
        u64 w = pack2s(W_edge[j * HIDDEN + k]);
        #pragma unroll
        for (int q = 0; q < 16; q++) {
            ulonglong2 s2 = *reinterpret_cast<const ulonglong2*>(&fs[j][4 * q]);
            acc[2 * q]     = fma2(s2.x, w, acc[2 * q]);
            acc[2 * q + 1] = fma2(s2.y, w, acc[2 * q + 1]);
        }
    }

    float csD = g_csD[k], bd = b_dih[k], be = b_edge[k];
    #pragma unroll
    for (int p = 0; p < 32; p++) {
        float2 va = unpack2(acc[p]);
        float a[2] = {va.x, va.y};
        #pragma unroll
        for (int l = 0; l < 2; l++) {
            int i = 2 * p + l;
            size_t e = (size_t)e0 + i;
            float dih  = dihs[i];
            float gate = sigmoidf_(dih * csD + bd);
            out[O_F   + e * HIDDEN + k] = fs[k][i] + (a[l] + be) * gate;
            out[O_DIH + e * HIDDEN + k] = dih;
        }
    }
}

// ---------------- launch ----------------
extern "C" void kernel_launch(void* const* d_in, const int* in_sizes, int n_in,
                              void* d_out, int out_size) {
    const float* h        = (const float*)d_in[0];
    const float* v        = (const float*)d_in[1];
    const float* f        = (const float*)d_in[2];
    const float* pos      = (const float*)d_in[3];
    const float* edge_rbf = (const float*)d_in[4];
    const int*   ei       = (const int*)  d_in[5];
    const float* W_msg    = (const float*)d_in[6];
    const float* b_msg    = (const float*)d_in[7];
    const float* W_vec    = (const float*)d_in[8];
    const float* b_vec    = (const float*)d_in[9];
    const float* W_scalar = (const float*)d_in[10];
    const float* b_scalar = (const float*)d_in[11];
    const float* W_edge   = (const float*)d_in[12];
    const float* b_edge   = (const float*)d_in[13];
    const float* W_ang    = (const float*)d_in[14];
    const float* b_ang    = (const float*)d_in[15];
    const float* W_dih    = (const float*)d_in[16];
    const float* b_dih    = (const float*)d_in[17];
    float* out = (float*)d_out;

    // v_updated starts as a copy of v (atomics accumulate on top)
    cudaMemcpyAsync(out + O_V, v, (size_t)N_NODES * 3 * HIDDEN * sizeof(float),
                    cudaMemcpyDeviceToDevice, 0);

    k_prepAll<<<307, 128>>>(W_msg, W_vec, W_ang, W_dih, b_msg, b_vec, out + O_DU);
    k_geom<<<(N_EDGES + 255) / 256, 256>>>(pos, ei, out + O_DU);
    k_node<<<N_NODES / 8, 128>>>(h, W_scalar, b_scalar, b_ang, out + O_DU, out);
    k_edge<<<N_EDGES / 32, 128>>>(v, ei, edge_rbf, out + O_V);
    k_fgate<<<N_EDGES / 64, 128>>>(f, ei, W_edge, b_edge, b_dih, out + O_DU, out);
}

// round 10
// speedup vs baseline: 1.1847x; 1.1847x over previous
#include <cuda_runtime.h>
#include <math.h>

#define N_NODES 25000
#define N_EDGES 400000
#define HIDDEN  128
#define NUM_RBF 50
#define CUTOFF_R 10.0f

// Output layout (floats): h_updated, v_updated, f_updated, angular_info, dihedral_info, direction_units
#define O_H   0
#define O_V   3200000
#define O_F   12800000
#define O_ANG 64000000
#define O_DIH 67200000
#define O_DU  118400000

// ---------------- scratch ----------------
__device__ float4 g_u4[N_EDGES];         // (ux, uy, uz, cutoff_w)
__device__ float g_hAV[N_NODES * 256];   // h @ (W_msgA @ W_vec)  (gathered at col)
__device__ float g_hBV[N_NODES * 256];   // h @ (W_msgB @ W_vec)  (gathered at row)
__device__ float g_WAV[128 * 256];
__device__ float g_WBV[128 * 256];
__device__ float g_WRV[NUM_RBF * 256];
__device__ float g_bV[256];              // b_msg @ W_vec + b_vec
__device__ float g_csA[HIDDEN];
__device__ float g_csD[HIDDEN];

typedef unsigned long long u64;

__device__ __forceinline__ u64 pack2s(float x) {   // (x, x)
    u64 r; unsigned int xi = __float_as_uint(x);
    asm("mov.b64 %0, {%1, %1};" : "=l"(r) : "r"(xi)); return r;
}
__device__ __forceinline__ u64 pack2(float lo, float hi) {
    u64 r; unsigned int l = __float_as_uint(lo), h = __float_as_uint(hi);
    asm("mov.b64 %0, {%1, %2};" : "=l"(r) : "r"(l), "r"(h)); return r;
}
__device__ __forceinline__ u64 fma2(u64 a, u64 b, u64 c) {
    u64 d; asm("fma.rn.f32x2 %0, %1, %2, %3;" : "=l"(d) : "l"(a), "l"(b), "l"(c)); return d;
}
__device__ __forceinline__ float2 unpack2(u64 a) {
    unsigned int l, h;
    asm("mov.b64 {%0, %1}, %2;" : "=r"(l), "=r"(h) : "l"(a));
    return make_float2(__uint_as_float(l), __uint_as_float(h));
}
__device__ __forceinline__ float sigmoidf_(float x) { return 1.0f / (1.0f + expf(-x)); }

// ---------------- K1: combined prep — du zero, W products, colsums, fused bias ----------------
__global__ void k_prepAll(const float* __restrict__ W_msg, const float* __restrict__ W_vec,
                          const float* __restrict__ W_ang, const float* __restrict__ W_dih,
                          const float* __restrict__ b_msg, const float* __restrict__ b_vec,
                          float* __restrict__ du) {
    int r = blockIdx.x;
    int k = threadIdx.x;
    for (int t = r * 128 + k; t < N_NODES * 3; t += 307 * 128) du[t] = 0.0f;

    if (r < 306) {
        __shared__ float wr[HIDDEN];
        wr[k] = W_msg[r * HIDDEN + k];
        __syncthreads();
        float a = 0.f, b = 0.f;
        #pragma unroll 4
        for (int t = 0; t < HIDDEN; t++) {
            float w = wr[t];
            a += w * W_vec[t * 256 + k];
            b += w * W_vec[t * 256 + 128 + k];
        }
        float* dst = (r < 128) ? &g_WAV[r * 256]
                   : (r < 256) ? &g_WBV[(r - 128) * 256]
                               : &g_WRV[(r - 256) * 256];
        dst[k] = a; dst[128 + k] = b;
    } else {
        float a = 0.f, d = 0.f, b1 = 0.f, b2 = 0.f;
        #pragma unroll 4
        for (int j = 0; j < HIDDEN; j++) {
            a += W_ang[j * HIDDEN + k];
            d += W_dih[j * HIDDEN + k];
            float bm = b_msg[j];
            b1 += bm * W_vec[j * 256 + k];
            b2 += bm * W_vec[j * 256 + 128 + k];
        }
        g_csA[k] = a; g_csD[k] = d;
        g_bV[k]       = b1 + b_vec[k];
        g_bV[128 + k] = b2 + b_vec[128 + k];
    }
}

// ---------------- K2: edge geometry + direction_units scatter ----------------
__global__ void k_geom(const float* __restrict__ pos, const int* __restrict__ ei,
                       float* __restrict__ du) {
    int e = blockIdx.x * blockDim.x + threadIdx.x;
    if (e >= N_EDGES) return;
    int r = ei[e];
    int c = ei[N_EDGES + e];
    float dx = pos[c * 3 + 0] - pos[r * 3 + 0];
    float dy = pos[c * 3 + 1] - pos[r * 3 + 1];
    float dz = pos[c * 3 + 2] - pos[r * 3 + 2];
    float dist = sqrtf(dx * dx + dy * dy + dz * dz) + 1e-8f;
    float inv = 1.0f / dist;
    float ux = dx * inv, uy = dy * inv, uz = dz * inv;
    float cw = (dist < CUTOFF_R)
             ? 0.5f * (cosf(3.14159265358979323846f * dist / CUTOFF_R) + 1.0f)
             : 0.0f;
    g_u4[e] = make_float4(ux, uy, uz, cw);
    atomicAdd(&du[r * 3 + 0],  ux);
    atomicAdd(&du[r * 3 + 1],  uy);
    atomicAdd(&du[r * 3 + 2],  uz);
    atomicAdd(&du[c * 3 + 0], -ux);
    atomicAdd(&du[c * 3 + 1], -uy);
    atomicAdd(&du[c * 3 + 2], -uz);
}

// ---------------- K3: per-node — hAV, hBV, h_updated, angular_info ----------------
// 8 nodes per block, 128 threads. Activations j-major; packed f32x2 over node pairs.
__global__ void __launch_bounds__(128) k_node(
        const float* __restrict__ h,
        const float* __restrict__ W_scalar,
        const float* __restrict__ b_scalar,
        const float* __restrict__ b_ang,
        const float* __restrict__ du,
        float* __restrict__ out) {
    int n0 = blockIdx.x * 8;           // N_NODES % 8 == 0
    int k = threadIdx.x;
    __shared__ __align__(16) float hs[HIDDEN][8];   // [j][node]
    __shared__ float angs[8];
    #pragma unroll
    for (int i = 0; i < 8; i++) hs[k][i] = h[(size_t)(n0 + i) * HIDDEN + k];
    if (k < 8) {
        int n = n0 + k;
        float x = du[n * 3 + 0], y = du[n * 3 + 1], z = du[n * 3 + 2];
        angs[k] = x * x + y * y + z * z;
    }
    __syncthreads();

    u64 aA1[4], aA2[4], aB1[4], aB2[4], aS[4];
    #pragma unroll
    for (int p = 0; p < 4; p++) { aA1[p]=0; aA2[p]=0; aB1[p]=0; aB2[p]=0; aS[p]=0; }

    #pragma unroll 2
    for (int j = 0; j < HIDDEN; j++) {
        u64 wA1 = pack2s(g_WAV[j * 256 + k]);
        u64 wA2 = pack2s(g_WAV[j * 256 + 128 + k]);
        u64 wB1 = pack2s(g_WBV[j * 256 + k]);
        u64 wB2 = pack2s(g_WBV[j * 256 + 128 + k]);
        u64 wS  = pack2s(W_scalar[j * HIDDEN + k]);
        ulonglong2 sa = *reinterpret_cast<const ulonglong2*>(&hs[j][0]);
        ulonglong2 sb = *reinterpret_cast<const ulonglong2*>(&hs[j][4]);
        u64 s[4] = {sa.x, sa.y, sb.x, sb.y};
        #pragma unroll
        for (int p = 0; p < 4; p++) {
            aA1[p] = fma2(s[p], wA1, aA1[p]);
            aA2[p] = fma2(s[p], wA2, aA2[p]);
            aB1[p] = fma2(s[p], wB1, aB1[p]);
            aB2[p] = fma2(s[p], wB2, aB2[p]);
            aS[p]  = fma2(s[p], wS,  aS[p]);
        }
    }

    float csA = g_csA[k], ba = b_ang[k], bs = b_scalar[k];
    #pragma unroll
    for (int p = 0; p < 4; p++) {
        float2 vA1 = unpack2(aA1[p]), vA2 = unpack2(aA2[p]);
        float2 vB1 = unpack2(aB1[p]), vB2 = unpack2(aB2[p]);
        float2 vS  = unpack2(aS[p]);
        float A1[2] = {vA1.x, vA1.y}, A2[2] = {vA2.x, vA2.y};
        float B1[2] = {vB1.x, vB1.y}, B2[2] = {vB2.x, vB2.y};
        float S [2] = {vS.x,  vS.y};
        #pragma unroll
        for (int l = 0; l < 2; l++) {
            int i = 2 * p + l;
            int n = n0 + i;
            g_hAV[(size_t)n * 256 + k]       = A1[l];
            g_hAV[(size_t)n * 256 + 128 + k] = A2[l];
            g_hBV[(size_t)n * 256 + k]       = B1[l];
            g_hBV[(size_t)n * 256 + 128 + k] = B2[l];
            float ang  = angs[i];
            float gate = sigmoidf_(ang * csA + ba);
            out[O_H   + (size_t)n * HIDDEN + k] = hs[k][i] + (S[l] + bs) * gate;
            out[O_ANG + (size_t)n * HIDDEN + k] = ang;
        }
    }
}

// ---------------- K4: fused vec path — gather-init + rbf mini-GEMM + vec_msg scatter ----------------
// 16 edges per block, 128 threads. Node gathers issued FIRST (into accumulator init),
// their latency hidden behind the 50-iteration rbf GEMM.
__global__ void __launch_bounds__(128) k_edge(
        const float* __restrict__ v, const int* __restrict__ ei,
        const float* __restrict__ rbf, float* __restrict__ out_v) {
    const int EB = 16;
    int e0 = blockIdx.x * EB;          // N_EDGES % 16 == 0
    int k = threadIdx.x;
    __shared__ __align__(16) float rs[NUM_RBF][EB];     // [rbf][edge]
    __shared__ __align__(16) float m[EB][3 * HIDDEN];   // messages
    __shared__ float4 s_u4[EB];
    __shared__ int s_row[EB], s_col[EB];

    if (k < EB) {
        int e = e0 + k;
        s_row[k] = ei[e]; s_col[k] = ei[N_EDGES + e];
        s_u4[k] = g_u4[e];
    }
    __syncthreads();   // indices ready before gather issue

    // Accumulators initialized with gathered node terms + bias — LDGs issue up front.
    float bV1 = g_bV[k], bV2 = g_bV[128 + k];
    u64 a1[8], a2[8];
    #pragma unroll
    for (int p = 0; p < 8; p++) {
        int eA = 2 * p, eB_ = 2 * p + 1;
        size_t cA = (size_t)s_col[eA] * 256, rA = (size_t)s_row[eA] * 256;
        size_t cB = (size_t)s_col[eB_] * 256, rB = (size_t)s_row[eB_] * 256;
        a1[p] = pack2(g_hAV[cA + k]       + g_hBV[rA + k]       + bV1,
                      g_hAV[cB + k]       + g_hBV[rB + k]       + bV1);
        a2[p] = pack2(g_hAV[cA + 128 + k] + g_hBV[rA + 128 + k] + bV2,
                      g_hAV[cB + 128 + k] + g_hBV[rB + 128 + k] + bV2);
    }

    // rbf tile load (after gathers issued; overlaps too)
    for (int t = k; t < EB * NUM_RBF; t += 128) {
        int i = t / NUM_RBF, r = t - i * NUM_RBF;
        rs[r][i] = rbf[(size_t)(e0 + i) * NUM_RBF + r];
    }
    __syncthreads();

    #pragma unroll 2
    for (int r = 0; r < NUM_RBF; r++) {
        u64 w1 = pack2s(g_WRV[r * 256 + k]);
        u64 w2 = pack2s(g_WRV[r * 256 + 128 + k]);
        #pragma unroll
        for (int q = 0; q < 4; q++) {
            ulonglong2 s2 = *reinterpret_cast<const ulonglong2*>(&rs[r][4 * q]);
            a1[2 * q]     = fma2(s2.x, w1, a1[2 * q]);
            a2[2 * q]     = fma2(s2.x, w2, a2[2 * q]);
            a1[2 * q + 1] = fma2(s2.y, w1, a1[2 * q + 1]);
            a2[2 * q + 1] = fma2(s2.y, w2, a2[2 * q + 1]);
        }
    }

    float v1[EB], v2[EB];
    #pragma unroll
    for (int p = 0; p < 8; p++) {
        float2 f1 = unpack2(a1[p]), f2 = unpack2(a2[p]);
        v1[2 * p] = f1.x; v1[2 * p + 1] = f1.y;
        v2[2 * p] = f2.x; v2[2 * p + 1] = f2.y;
    }

    #pragma unroll 4
    for (int i = 0; i < EB; i++) {
        int r_ = s_row[i];
        float4 u = s_u4[i];
        float w1 = v1[i] * u.w;
        float w2 = v2[i] * u.w;
        const float* vr = v + (size_t)r_ * 3 * HIDDEN;
        m[i][k]              = w1 * u.x + w2 * vr[k];
        m[i][HIDDEN + k]     = w1 * u.y + w2 * vr[HIDDEN + k];
        m[i][2 * HIDDEN + k] = w1 * u.z + w2 * vr[2 * HIDDEN + k];
    }
    __syncthreads();

    for (int t = k; t < EB * 96; t += 128) {
        int i = t / 96, q = t - i * 96;
        float4 val = *reinterpret_cast<float4*>(&m[i][q * 4]);
        int c_ = s_col[i];
        atomicAdd(reinterpret_cast<float4*>(out_v + (size_t)c_ * 3 * HIDDEN + q * 4), val);
    }
}

// ---------------- K5: dihedral + f gating — 32 edges/block, packed f32x2 ----------------
__global__ void __launch_bounds__(128) k_fgate(
        const float* __restrict__ f, const int* __restrict__ ei,
        const float* __restrict__ W_edge, const float* __restrict__ b_edge,
        const float* __restrict__ b_dih, const float* __restrict__ du,
        float* __restrict__ out) {
    int e0 = blockIdx.x * 32;          // N_EDGES % 32 == 0
    int k = threadIdx.x;
    __shared__ __align__(16) float fs[HIDDEN][32];   // [j][edge]
    __shared__ float dihs[32];
    #pragma unroll
    for (int i = 0; i < 32; i++) fs[k][i] = f[(size_t)(e0 + i) * HIDDEN + k];
    if (k < 32) {
        int e = e0 + k;
        int r = ei[e], c = ei[N_EDGES + e];
        float4 u = g_u4[e];
        float vix = du[r * 3 + 0], viy = du[r * 3 + 1], viz = du[r * 3 + 2];
        float vjx = du[c * 3 + 0], vjy = du[c * 3 + 1], vjz = du[c * 3 + 2];
        float di = vix * u.x + viy * u.y + viz * u.z;
        float dj = vjx * u.x + vjy * u.y + vjz * u.z;
        float ax = vix - di * u.x, ay = viy - di * u.y, az = viz - di * u.z;
        float bx = vjx - dj * u.x, by = vjy - dj * u.y, bz = vjz - dj * u.z;
        dihs[k] = ax * bx + ay * by + az * bz;
    }
    __syncthreads();

    u64 acc[16];
    #pragma unroll
    for (int p = 0; p < 16; p++) acc[p] = 0;

    #pragma unroll 2
    for (int j = 0; j < HIDDEN; j++) {
        u64 w = pack2s(W_edge[j * HIDDEN + k]);
        #pragma unroll
        for (int q = 0; q < 8; q++) {
            ulonglong2 s2 = *reinterpret_cast<const ulonglong2*>(&fs[j][4 * q]);
            acc[2 * q]     = fma2(s2.x, w, acc[2 * q]);
            acc[2 * q + 1] = fma2(s2.y, w, acc[2 * q + 1]);
        }
    }

    float csD = g_csD[k], bd = b_dih[k], be = b_edge[k];
    #pragma unroll
    for (int p = 0; p < 16; p++) {
        float2 va = unpack2(acc[p]);
        float a[2] = {va.x, va.y};
        #pragma unroll
        for (int l = 0; l < 2; l++) {
            int i = 2 * p + l;
            size_t e = (size_t)e0 + i;
            float dih  = dihs[i];
            float gate = sigmoidf_(dih * csD + bd);
            out[O_F   + e * HIDDEN + k] = fs[k][i] + (a[l] + be) * gate;
            out[O_DIH + e * HIDDEN + k] = dih;
        }
    }
}

// ---------------- launch ----------------
extern "C" void kernel_launch(void* const* d_in, const int* in_sizes, int n_in,
                              void* d_out, int out_size) {
    const float* h        = (const float*)d_in[0];
    const float* v        = (const float*)d_in[1];
    const float* f        = (const float*)d_in[2];
    const float* pos      = (const float*)d_in[3];
    const float* edge_rbf = (const float*)d_in[4];
    const int*   ei       = (const int*)  d_in[5];
    const float* W_msg    = (const float*)d_in[6];
    const float* b_msg    = (const float*)d_in[7];
    const float* W_vec    = (const float*)d_in[8];
    const float* b_vec    = (const float*)d_in[9];
    const float* W_scalar = (const float*)d_in[10];
    const float* b_scalar = (const float*)d_in[11];
    const float* W_edge   = (const float*)d_in[12];
    const float* b_edge   = (const float*)d_in[13];
    const float* W_ang    = (const float*)d_in[14];
    const float* b_ang    = (const float*)d_in[15];
    const float* W_dih    = (const float*)d_in[16];
    const float* b_dih    = (const float*)d_in[17];
    float* out = (float*)d_out;

    // v_updated starts as a copy of v (atomics accumulate on top)
    cudaMemcpyAsync(out + O_V, v, (size_t)N_NODES * 3 * HIDDEN * sizeof(float),
                    cudaMemcpyDeviceToDevice, 0);

    k_prepAll<<<307, 128>>>(W_msg, W_vec, W_ang, W_dih, b_msg, b_vec, out + O_DU);
    k_geom<<<(N_EDGES + 255) / 256, 256>>>(pos, ei, out + O_DU);
    k_node<<<N_NODES / 8, 128>>>(h, W_scalar, b_scalar, b_ang, out + O_DU, out);
    k_edge<<<N_EDGES / 16, 128>>>(v, ei, edge_rbf, out + O_V);
    k_fgate<<<N_EDGES / 32, 128>>>(f, ei, W_edge, b_edge, b_dih, out + O_DU, out);
}

// round 12
// speedup vs baseline: 1.1909x; 1.0052x over previous
#include <cuda_runtime.h>
#include <math.h>

#define N_NODES 25000
#define N_EDGES 400000
#define HIDDEN  128
#define NUM_RBF 50
#define CUTOFF_R 10.0f

// Output layout (floats): h_updated, v_updated, f_updated, angular_info, dihedral_info, direction_units
#define O_H   0
#define O_V   3200000
#define O_F   12800000
#define O_ANG 64000000
#define O_DIH 67200000
#define O_DU  118400000

// ---------------- scratch ----------------
__device__ float4 g_u4[N_EDGES];         // (ux, uy, uz, cutoff_w)
__device__ float g_hAV[N_NODES * 256];   // h @ (W_msgA @ W_vec)  (gathered at col)
__device__ float g_hBV[N_NODES * 256];   // h @ (W_msgB @ W_vec)  (gathered at row)
__device__ float g_WAV[128 * 256];
__device__ float g_WBV[128 * 256];
__device__ float g_WRV[NUM_RBF * 256];
__device__ float g_bV[256];              // b_msg @ W_vec + b_vec
__device__ float g_csA[HIDDEN];
__device__ float g_csD[HIDDEN];
__device__ int   g_cnt[N_NODES];         // per-col edge counts
__device__ int   g_cur[N_NODES];         // scatter cursors
__device__ int   g_perm[N_EDGES];        // edge ids sorted by col

typedef unsigned long long u64;

__device__ __forceinline__ u64 pack2s(float x) {   // (x, x)
    u64 r; unsigned int xi = __float_as_uint(x);
    asm("mov.b64 %0, {%1, %1};" : "=l"(r) : "r"(xi)); return r;
}
__device__ __forceinline__ u64 pack2(float lo, float hi) {
    u64 r; unsigned int l = __float_as_uint(lo), h = __float_as_uint(hi);
    asm("mov.b64 %0, {%1, %2};" : "=l"(r) : "r"(l), "r"(h)); return r;
}
__device__ __forceinline__ u64 fma2(u64 a, u64 b, u64 c) {
    u64 d; asm("fma.rn.f32x2 %0, %1, %2, %3;" : "=l"(d) : "l"(a), "l"(b), "l"(c)); return d;
}
__device__ __forceinline__ float2 unpack2(u64 a) {
    unsigned int l, h;
    asm("mov.b64 {%0, %1}, %2;" : "=r"(l), "=r"(h) : "l"(a));
    return make_float2(__uint_as_float(l), __uint_as_float(h));
}
__device__ __forceinline__ float sigmoidf_(float x) { return 1.0f / (1.0f + expf(-x)); }

// ---------------- K1: combined prep — du/cnt zero, W products, colsums, fused bias ----------------
__global__ void k_prepAll(const float* __restrict__ W_msg, const float* __restrict__ W_vec,
                          const float* __restrict__ W_ang, const float* __restrict__ W_dih,
                          const float* __restrict__ b_msg, const float* __restrict__ b_vec,
                          float* __restrict__ du) {
    int r = blockIdx.x;
    int k = threadIdx.x;
    for (int t = r * 128 + k; t < N_NODES * 3; t += 307 * 128) du[t] = 0.0f;
    for (int t = r * 128 + k; t < N_NODES; t += 307 * 128) g_cnt[t] = 0;

    if (r < 306) {
        __shared__ float wr[HIDDEN];
        wr[k] = W_msg[r * HIDDEN + k];
        __syncthreads();
        float a = 0.f, b = 0.f;
        #pragma unroll 4
        for (int t = 0; t < HIDDEN; t++) {
            float w = wr[t];
            a += w * W_vec[t * 256 + k];
            b += w * W_vec[t * 256 + 128 + k];
        }
        float* dst = (r < 128) ? &g_WAV[r * 256]
                   : (r < 256) ? &g_WBV[(r - 128) * 256]
                               : &g_WRV[(r - 256) * 256];
        dst[k] = a; dst[128 + k] = b;
    } else {
        float a = 0.f, d = 0.f, b1 = 0.f, b2 = 0.f;
        #pragma unroll 4
        for (int j = 0; j < HIDDEN; j++) {
            a += W_ang[j * HIDDEN + k];
            d += W_dih[j * HIDDEN + k];
            float bm = b_msg[j];
            b1 += bm * W_vec[j * 256 + k];
            b2 += bm * W_vec[j * 256 + 128 + k];
        }
        g_csA[k] = a; g_csD[k] = d;
        g_bV[k]       = b1 + b_vec[k];
        g_bV[128 + k] = b2 + b_vec[128 + k];
    }
}

// ---------------- sort by col: histogram -> scan -> scatter ----------------
__global__ void k_hist(const int* __restrict__ ei) {
    int e = blockIdx.x * blockDim.x + threadIdx.x;
    if (e < N_EDGES) atomicAdd(&g_cnt[ei[N_EDGES + e]], 1);
}

__global__ void k_scan() {           // single block, 256 threads
    __shared__ int part[256];
    int t = threadIdx.x;
    const int CH = (N_NODES + 255) / 256;   // 98
    int base = t * CH;
    int sum = 0;
    for (int i = 0; i < CH; i++) {
        int c = base + i;
        if (c < N_NODES) sum += g_cnt[c];
    }
    part[t] = sum;
    __syncthreads();
    // inclusive Hillis-Steele scan
    for (int off = 1; off < 256; off <<= 1) {
        int v = (t >= off) ? part[t - off] : 0;
        __syncthreads();
        part[t] += v;
        __syncthreads();
    }
    int run = part[t] - sum;   // exclusive prefix for this chunk
    for (int i = 0; i < CH; i++) {
        int c = base + i;
        if (c < N_NODES) { g_cur[c] = run; run += g_cnt[c]; }
    }
}

__global__ void k_scatterIds(const int* __restrict__ ei) {
    int e = blockIdx.x * blockDim.x + threadIdx.x;
    if (e < N_EDGES) {
        int pos = atomicAdd(&g_cur[ei[N_EDGES + e]], 1);
        g_perm[pos] = e;
    }
}

// ---------------- K2: edge geometry + direction_units scatter ----------------
__global__ void k_geom(const float* __restrict__ pos, const int* __restrict__ ei,
                       float* __restrict__ du) {
    int e = blockIdx.x * blockDim.x + threadIdx.x;
    if (e >= N_EDGES) return;
    int r = ei[e];
    int c = ei[N_EDGES + e];
    float dx = pos[c * 3 + 0] - pos[r * 3 + 0];
    float dy = pos[c * 3 + 1] - pos[r * 3 + 1];
    float dz = pos[c * 3 + 2] - pos[r * 3 + 2];
    float dist = sqrtf(dx * dx + dy * dy + dz * dz) + 1e-8f;
    float inv = 1.0f / dist;
    float ux = dx * inv, uy = dy * inv, uz = dz * inv;
    float cw = (dist < CUTOFF_R)
             ? 0.5f * (cosf(3.14159265358979323846f * dist / CUTOFF_R) + 1.0f)
             : 0.0f;
    g_u4[e] = make_float4(ux, uy, uz, cw);
    atomicAdd(&du[r * 3 + 0],  ux);
    atomicAdd(&du[r * 3 + 1],  uy);
    atomicAdd(&du[r * 3 + 2],  uz);
    atomicAdd(&du[c * 3 + 0], -ux);
    atomicAdd(&du[c * 3 + 1], -uy);
    atomicAdd(&du[c * 3 + 2], -uz);
}

// ---------------- K3: per-node — hAV, hBV, h_updated, angular_info ----------------
__global__ void __launch_bounds__(128) k_node(
        const float* __restrict__ h,
        const float* __restrict__ W_scalar,
        const float* __restrict__ b_scalar,
        const float* __restrict__ b_ang,
        const float* __restrict__ du,
        float* __restrict__ out) {
    int n0 = blockIdx.x * 8;           // N_NODES % 8 == 0
    int k = threadIdx.x;
    __shared__ __align__(16) float hs[HIDDEN][8];   // [j][node]
    __shared__ float angs[8];
    #pragma unroll
    for (int i = 0; i < 8; i++) hs[k][i] = h[(size_t)(n0 + i) * HIDDEN + k];
    if (k < 8) {
        int n = n0 + k;
        float x = du[n * 3 + 0], y = du[n * 3 + 1], z = du[n * 3 + 2];
        angs[k] = x * x + y * y + z * z;
    }
    __syncthreads();

    u64 aA1[4], aA2[4], aB1[4], aB2[4], aS[4];
    #pragma unroll
    for (int p = 0; p < 4; p++) { aA1[p]=0; aA2[p]=0; aB1[p]=0; aB2[p]=0; aS[p]=0; }

    #pragma unroll 2
    for (int j = 0; j < HIDDEN; j++) {
        u64 wA1 = pack2s(g_WAV[j * 256 + k]);
        u64 wA2 = pack2s(g_WAV[j * 256 + 128 + k]);
        u64 wB1 = pack2s(g_WBV[j * 256 + k]);
        u64 wB2 = pack2s(g_WBV[j * 256 + 128 + k]);
        u64 wS  = pack2s(W_scalar[j * HIDDEN + k]);
        ulonglong2 sa = *reinterpret_cast<const ulonglong2*>(&hs[j][0]);
        ulonglong2 sb = *reinterpret_cast<const ulonglong2*>(&hs[j][4]);
        u64 s[4] = {sa.x, sa.y, sb.x, sb.y};
        #pragma unroll
        for (int p = 0; p < 4; p++) {
            aA1[p] = fma2(s[p], wA1, aA1[p]);
            aA2[p] = fma2(s[p], wA2, aA2[p]);
            aB1[p] = fma2(s[p], wB1, aB1[p]);
            aB2[p] = fma2(s[p], wB2, aB2[p]);
            aS[p]  = fma2(s[p], wS,  aS[p]);
        }
    }

    float csA = g_csA[k], ba = b_ang[k], bs = b_scalar[k];
    #pragma unroll
    for (int p = 0; p < 4; p++) {
        float2 vA1 = unpack2(aA1[p]), vA2 = unpack2(aA2[p]);
        float2 vB1 = unpack2(aB1[p]), vB2 = unpack2(aB2[p]);
        float2 vS  = unpack2(aS[p]);
        float A1[2] = {vA1.x, vA1.y}, A2[2] = {vA2.x, vA2.y};
        float B1[2] = {vB1.x, vB1.y}, B2[2] = {vB2.x, vB2.y};
        float S [2] = {vS.x,  vS.y};
        #pragma unroll
        for (int l = 0; l < 2; l++) {
            int i = 2 * p + l;
            int n = n0 + i;
            g_hAV[(size_t)n * 256 + k]       = A1[l];
            g_hAV[(size_t)n * 256 + 128 + k] = A2[l];
            g_hBV[(size_t)n * 256 + k]       = B1[l];
            g_hBV[(size_t)n * 256 + 128 + k] = B2[l];
            float ang  = angs[i];
            float gate = sigmoidf_(ang * csA + ba);
            out[O_H   + (size_t)n * HIDDEN + k] = hs[k][i] + (S[l] + bs) * gate;
            out[O_ANG + (size_t)n * HIDDEN + k] = ang;
        }
    }
}

// ---------------- K4: fused vec path over col-sorted edges ----------------
// 16 edges per block (from g_perm), 128 threads.
__global__ void __launch_bounds__(128) k_edge(
        const float* __restrict__ v, const int* __restrict__ ei,
        const float* __restrict__ rbf, float* __restrict__ out_v) {
    const int EB = 16;
    int e0 = blockIdx.x * EB;          // N_EDGES % 16 == 0
    int k = threadIdx.x;
    __shared__ __align__(16) float rs[NUM_RBF][EB];     // [rbf][edge]
    __shared__ __align__(16) float m[EB][3 * HIDDEN];   // messages
    __shared__ float4 s_u4[EB];
    __shared__ int s_row[EB], s_col[EB], s_eidx[EB];

    if (k < EB) {
        int eidx = g_perm[e0 + k];
        s_eidx[k] = eidx;
        s_row[k] = ei[eidx]; s_col[k] = ei[N_EDGES + eidx];
        s_u4[k] = g_u4[eidx];
    }
    __syncthreads();   // indices ready before gather issue

    // Accumulators initialized with gathered node terms + bias — LDGs issue up front.
    float bV1 = g_bV[k], bV2 = g_bV[128 + k];
    u64 a1[8], a2[8];
    #pragma unroll
    for (int p = 0; p < 8; p++) {
        int eA = 2 * p, eB_ = 2 * p + 1;
        size_t cA = (size_t)s_col[eA] * 256, rA = (size_t)s_row[eA] * 256;
        size_t cB = (size_t)s_col[eB_] * 256, rB = (size_t)s_row[eB_] * 256;
        a1[p] = pack2(g_hAV[cA + k]       + g_hBV[rA + k]       + bV1,
                      g_hAV[cB + k]       + g_hBV[rB + k]       + bV1);
        a2[p] = pack2(g_hAV[cA + 128 + k] + g_hBV[rA + 128 + k] + bV2,
                      g_hAV[cB + 128 + k] + g_hBV[rB + 128 + k] + bV2);
    }

    // rbf tile load (permuted rows)
    for (int t = k; t < EB * NUM_RBF; t += 128) {
        int i = t / NUM_RBF, r = t - i * NUM_RBF;
        rs[r][i] = rbf[(size_t)s_eidx[i] * NUM_RBF + r];
    }
    __syncthreads();

    #pragma unroll 2
    for (int r = 0; r < NUM_RBF; r++) {
        u64 w1 = pack2s(g_WRV[r * 256 + k]);
        u64 w2 = pack2s(g_WRV[r * 256 + 128 + k]);
        #pragma unroll
        for (int q = 0; q < 4; q++) {
            ulonglong2 s2 = *reinterpret_cast<const ulonglong2*>(&rs[r][4 * q]);
            a1[2 * q]     = fma2(s2.x, w1, a1[2 * q]);
            a2[2 * q]     = fma2(s2.x, w2, a2[2 * q]);
            a1[2 * q + 1] = fma2(s2.y, w1, a1[2 * q + 1]);
            a2[2 * q + 1] = fma2(s2.y, w2, a2[2 * q + 1]);
        }
    }

    float v1[EB], v2[EB];
    #pragma unroll
    for (int p = 0; p < 8; p++) {
        float2 f1 = unpack2(a1[p]), f2 = unpack2(a2[p]);
        v1[2 * p] = f1.x; v1[2 * p + 1] = f1.y;
        v2[2 * p] = f2.x; v2[2 * p + 1] = f2.y;
    }

    #pragma unroll 4
    for (int i = 0; i < EB; i++) {
        int r_ = s_row[i];
        float4 u = s_u4[i];
        float w1 = v1[i] * u.w;
        float w2 = v2[i] * u.w;
        const float* vr = v + (size_t)r_ * 3 * HIDDEN;
        m[i][k]              = w1 * u.x + w2 * vr[k];
        m[i][HIDDEN + k]     = w1 * u.y + w2 * vr[HIDDEN + k];
        m[i][2 * HIDDEN + k] = w1 * u.z + w2 * vr[2 * HIDDEN + k];
    }
    __syncthreads();

    for (int t = k; t < EB * 96; t += 128) {
        int i = t / 96, q = t - i * 96;
        float4 val = *reinterpret_cast<float4*>(&m[i][q * 4]);
        int c_ = s_col[i];
        atomicAdd(reinterpret_cast<float4*>(out_v + (size_t)c_ * 3 * HIDDEN + q * 4), val);
    }
}

// ---------------- K5: dihedral + f gating — 32 edges/block, packed f32x2 ----------------
__global__ void __launch_bounds__(128) k_fgate(
        const float* __restrict__ f, const int* __restrict__ ei,
        const float* __restrict__ W_edge, const float* __restrict__ b_edge,
        const float* __restrict__ b_dih, const float* __restrict__ du,
        float* __restrict__ out) {
    int e0 = blockIdx.x * 32;          // N_EDGES % 32 == 0
    int k = threadIdx.x;
    __shared__ __align__(16) float fs[HIDDEN][32];   // [j][edge]
    __shared__ float dihs[32];
    #pragma unroll
    for (int i = 0; i < 32; i++) fs[k][i] = f[(size_t)(e0 + i) * HIDDEN + k];
    if (k < 32) {
        int e = e0 + k;
        int r = ei[e], c = ei[N_EDGES + e];
        float4 u = g_u4[e];
        float vix = du[r * 3 + 0], viy = du[r * 3 + 1], viz = du[r * 3 + 2];
        float vjx = du[c * 3 + 0], vjy = du[c * 3 + 1], vjz = du[c * 3 + 2];
        float di = vix * u.x + viy * u.y + viz * u.z;
        float dj = vjx * u.x + vjy * u.y + vjz * u.z;
        float ax = vix - di * u.x, ay = viy - di * u.y, az = viz - di * u.z;
        float bx = vjx - dj * u.x, by = vjy - dj * u.y, bz = vjz - dj * u.z;
        dihs[k] = ax * bx + ay * by + az * bz;
    }
    __syncthreads();

    u64 acc[16];
    #pragma unroll
    for (int p = 0; p < 16; p++) acc[p] = 0;

    #pragma unroll 2
    for (int j = 0; j < HIDDEN; j++) {
        u64 w = pack2s(W_edge[j * HIDDEN + k]);
        #pragma unroll
        for (int q = 0; q < 8; q++) {
            ulonglong2 s2 = *reinterpret_cast<const ulonglong2*>(&fs[j][4 * q]);
            acc[2 * q]     = fma2(s2.x, w, acc[2 * q]);
            acc[2 * q + 1] = fma2(s2.y, w, acc[2 * q + 1]);
        }
    }

    float csD = g_csD[k], bd = b_dih[k], be = b_edge[k];
    #pragma unroll
    for (int p = 0; p < 16; p++) {
        float2 va = unpack2(acc[p]);
        float a[2] = {va.x, va.y};
        #pragma unroll
        for (int l = 0; l < 2; l++) {
            int i = 2 * p + l;
            size_t e = (size_t)e0 + i;
            float dih  = dihs[i];
            float gate = sigmoidf_(dih * csD + bd);
            out[O_F   + e * HIDDEN + k] = fs[k][i] + (a[l] + be) * gate;
            out[O_DIH + e * HIDDEN + k] = dih;
        }
    }
}

// ---------------- launch ----------------
extern "C" void kernel_launch(void* const* d_in, const int* in_sizes, int n_in,
                              void* d_out, int out_size) {
    const float* h        = (const float*)d_in[0];
    const float* v        = (const float*)d_in[1];
    const float* f        = (const float*)d_in[2];
    const float* pos      = (const float*)d_in[3];
    const float* edge_rbf = (const float*)d_in[4];
    const int*   ei       = (const int*)  d_in[5];
    const float* W_msg    = (const float*)d_in[6];
    const float* b_msg    = (const float*)d_in[7];
    const float* W_vec    = (const float*)d_in[8];
    const float* b_vec    = (const float*)d_in[9];
    const float* W_scalar = (const float*)d_in[10];
    const float* b_scalar = (const float*)d_in[11];
    const float* W_edge   = (const float*)d_in[12];
    const float* b_edge   = (const float*)d_in[13];
    const float* W_ang    = (const float*)d_in[14];
    const float* b_ang    = (const float*)d_in[15];
    const float* W_dih    = (const float*)d_in[16];
    const float* b_dih    = (const float*)d_in[17];
    float* out = (float*)d_out;

    // v_updated starts as a copy of v (atomics accumulate on top)
    cudaMemcpyAsync(out + O_V, v, (size_t)N_NODES * 3 * HIDDEN * sizeof(float),
                    cudaMemcpyDeviceToDevice, 0);

    k_prepAll<<<307, 128>>>(W_msg, W_vec, W_ang, W_dih, b_msg, b_vec, out + O_DU);
    k_hist<<<(N_EDGES + 255) / 256, 256>>>(ei);
    k_scan<<<1, 256>>>();
    k_scatterIds<<<(N_EDGES + 255) / 256, 256>>>(ei);
    k_geom<<<(N_EDGES + 255) / 256, 256>>>(pos, ei, out + O_DU);
    k_node<<<N_NODES / 8, 128>>>(h, W_scalar, b_scalar, b_ang, out + O_DU, out);
    k_edge<<<N_EDGES / 16, 128>>>(v, ei, edge_rbf, out + O_V);
    k_fgate<<<N_EDGES / 32, 128>>>(f, ei, W_edge, b_edge, b_dih, out + O_DU, out);
}